// round 1
// baseline (speedup 1.0000x reference)
#include <cuda_runtime.h>

#define NB 256
#define NT 1024
#define NL 64

// Per-batch loss scratch (static device global — no allocation).
__device__ float g_loss[NB];

__device__ __forceinline__ float warp_sum(float v) {
#pragma unroll
    for (int o = 16; o; o >>= 1) v += __shfl_xor_sync(0xffffffffu, v, o);
    return v;
}

// One scan step. u (register) holds e^{prev[c] - M}; E column packed in Ep as f32x2 pairs.
// Phase1: publish u, precompute e^{emit}; bar; Phase2: matvec via fma.rn.f32x2, rescale by 1/u[0].
#define CRF_STEP(t, eraw) do {                                                         \
    const int buf_ = (t) & 1;                                                          \
    sv[sub][buf_][c] = u;                                                              \
    const int tg_ = tg_sh[sub][(t)];                                                   \
    const float ee_ = __expf(eraw);                                                    \
    __syncthreads();                                                                   \
    const unsigned sva_ = svb + (unsigned)(buf_ * (NL * 4));                           \
    const float u0_ = sv[sub][buf_][0];                                                \
    const float r_ = 1.0f / u0_;                                                       \
    unsigned long long a0_ = 0ull, a1_ = 0ull, a2_ = 0ull, a3_ = 0ull;                 \
    _Pragma("unroll")                                                                  \
    for (int i_ = 0; i_ < 16; i_++) {                                                  \
        unsigned long long va_, vb_;                                                   \
        asm volatile("ld.shared.v2.u64 {%0, %1}, [%2];"                                \
                     : "=l"(va_), "=l"(vb_) : "r"(sva_ + 16u * i_));                   \
        if (i_ & 1) {                                                                  \
            asm("fma.rn.f32x2 %0, %1, %2, %0;" : "+l"(a2_) : "l"(va_), "l"(Ep[2*i_]));   \
            asm("fma.rn.f32x2 %0, %1, %2, %0;" : "+l"(a3_) : "l"(vb_), "l"(Ep[2*i_+1])); \
        } else {                                                                       \
            asm("fma.rn.f32x2 %0, %1, %2, %0;" : "+l"(a0_) : "l"(va_), "l"(Ep[2*i_]));   \
            asm("fma.rn.f32x2 %0, %1, %2, %0;" : "+l"(a1_) : "l"(vb_), "l"(Ep[2*i_+1])); \
        }                                                                              \
    }                                                                                  \
    asm("add.rn.f32x2 %0, %0, %1;" : "+l"(a0_) : "l"(a2_));                            \
    asm("add.rn.f32x2 %0, %0, %1;" : "+l"(a1_) : "l"(a3_));                            \
    asm("add.rn.f32x2 %0, %0, %1;" : "+l"(a0_) : "l"(a1_));                            \
    float lo_, hi_;                                                                    \
    asm("mov.b64 {%0, %1}, %2;" : "=f"(lo_), "=f"(hi_) : "l"(a0_));                    \
    u = (lo_ + hi_) * ee_ * r_;                                                        \
    Mac += (double)__logf(u0_);                                                        \
    if (c == tg_) gold += (eraw) + tm_sh[c * NL + tgprev];                             \
    tgprev = tg_;                                                                      \
} while (0)

__global__ __launch_bounds__(128, 1) void crf_forward_kernel(
    const float* __restrict__ scores, const int* __restrict__ targets,
    const float* __restrict__ startv, const float* __restrict__ Tmat,
    const float* __restrict__ endv)
{
    __shared__ float tm_sh[NL * NL];      // raw T_mat for gold-path transition gather
    __shared__ int   tg_sh[2][NT];        // targets per batch
    __shared__ float sv[2][2][NL];        // double-buffered u vector per batch
    __shared__ float sh_m[2];
    __shared__ float red[2][4];

    const int tid  = threadIdx.x;
    const int sub  = tid >> 6;            // batch within CTA (0/1)
    const int c    = tid & 63;            // state index owned by this lane
    const int b    = blockIdx.x * 2 + sub;
    const int warp = tid >> 5;
    const int lane = tid & 31;

    for (int i = tid; i < NL * NL; i += 128) tm_sh[i] = Tmat[i];
    for (int i = c; i < NT; i += NL) tg_sh[sub][i] = targets[b * NT + i];

    // E column for this lane: Ep[j] packs (exp(T_mat[c][2j]), exp(T_mat[c][2j+1]))
    // (Ttr[p][c] = T_mat[c][p], so lane c reads row c of T_mat — contiguous.)
    unsigned long long Ep[NL / 2];
#pragma unroll
    for (int j = 0; j < NL / 2; j++) {
        float e0 = __expf(Tmat[c * NL + 2 * j]);
        float e1 = __expf(Tmat[c * NL + 2 * j + 1]);
        asm("mov.b64 %0, {%1, %2};" : "=l"(Ep[j]) : "f"(e0), "f"(e1));
    }

    // t = 0 init
    const float emit0 = scores[(b * NT + 0) * NL + c];
    const float prev0 = startv[c] + emit0;
    float gold = 0.0f;
    int tgprev = targets[b * NT];
    if (c == tgprev) gold = startv[c] + emit0;
    if (c == 0) sh_m[sub] = prev0;
    __syncthreads();
    const float m0 = sh_m[sub];
    float u = __expf(prev0 - m0);
    double Mac = (double)m0;

    const unsigned svb = (unsigned)__cvta_generic_to_shared(&sv[sub][0][0]);

    // prefetch emits for t = 1..4
    float e0r = scores[(b * NT + 1) * NL + c];
    float e1r = scores[(b * NT + 2) * NL + c];
    float e2r = scores[(b * NT + 3) * NL + c];
    float e3r = scores[(b * NT + 4) * NL + c];

    int t = 1;
#pragma unroll 1
    for (; t <= NT - 7; t += 4) {  // full chunks cover t = 1..1020
        CRF_STEP(t,     e0r); e0r = scores[(b * NT + t + 4) * NL + c];
        CRF_STEP(t + 1, e1r); e1r = scores[(b * NT + t + 5) * NL + c];
        CRF_STEP(t + 2, e2r); e2r = scores[(b * NT + t + 6) * NL + c];
        CRF_STEP(t + 3, e3r); e3r = (t + 7 <= NT - 1)
                                    ? scores[(b * NT + t + 7) * NL + c] : 0.0f;
    }
    // remainder: t = 1021, 1022, 1023
    CRF_STEP(1021, e0r);
    CRF_STEP(1022, e1r);
    CRF_STEP(1023, e2r);

    __syncthreads();

    // normalizer = Mac + log( sum_c u[c] * e^{end[c]} )
    const float wv = u * __expf(endv[c]);
    if (c == tgprev) gold += endv[c];   // end-state contribution to gold path
    const float s1 = warp_sum(wv);
    const float g1 = warp_sum(gold);
    if (lane == 0) { red[sub][warp & 1] = s1; red[sub][2 + (warp & 1)] = g1; }
    __syncthreads();
    if (c == 0) {
        const float ssum = red[sub][0] + red[sub][1];
        const float gg   = red[sub][2] + red[sub][3];
        g_loss[b] = (float)(Mac + (double)__logf(ssum)) - gg;
    }
}

__global__ void crf_reduce_kernel(float* __restrict__ out) {
    __shared__ float w[8];
    const int i = threadIdx.x;
    float v = g_loss[i];
#pragma unroll
    for (int o = 16; o; o >>= 1) v += __shfl_xor_sync(0xffffffffu, v, o);
    if ((i & 31) == 0) w[i >> 5] = v;
    __syncthreads();
    if (i == 0) {
        float s = 0.0f;
#pragma unroll
        for (int k = 0; k < 8; k++) s += w[k];
        out[0] = s * (1.0f / (float)NB);
    }
}

extern "C" void kernel_launch(void* const* d_in, const int* in_sizes, int n_in,
                              void* d_out, int out_size)
{
    const float* scores  = (const float*)d_in[0];
    const int*   targets = (const int*)d_in[1];
    const float* startv  = (const float*)d_in[2];
    const float* Tmat    = (const float*)d_in[3];
    const float* endv    = (const float*)d_in[4];

    crf_forward_kernel<<<NB / 2, 128>>>(scores, targets, startv, Tmat, endv);
    crf_reduce_kernel<<<1, NB>>>((float*)d_out);
}

// round 3
// speedup vs baseline: 1.0330x; 1.0330x over previous
#include <cuda_runtime.h>

#define NB 256
#define NT 1024
#define NL 64

__device__ float g_loss[NB];

__device__ __forceinline__ float warp_sum(float v) {
#pragma unroll
    for (int k = 16; k; k >>= 1) v += __shfl_xor_sync(0xffffffffu, v, k);
    return v;
}

// One scan step. u(t-1) lives in smem buf[(PAR)^1]; we write u(t) to buf[PAR].
// Lane pair (kh=0, kh=1) splits the 64-long dot product; combine via shfl_xor(1).
// RESC: rescale by 1/u[0] and accumulate log into Mac (every 4th step).
#define CRF_STEP(t, PAR, eraw, RESC) do {                                              \
    const int tg_ = tg_sh[sub][(t)];                                                   \
    const float ee_ = __expf(eraw);                                                    \
    __syncthreads();                                                                   \
    const unsigned rb_ = ub + (unsigned)(((PAR) ^ 1) * 288);                           \
    float r_ = 1.0f;                                                                   \
    if (RESC) {                                                                        \
        float u0_;                                                                     \
        asm volatile("ld.shared.f32 %0, [%1];" : "=f"(u0_) : "r"(rb_));                \
        asm("rcp.approx.f32 %0, %1;" : "=f"(r_) : "f"(u0_));                           \
        Mac += (double)__logf(u0_);                                                    \
    }                                                                                  \
    unsigned long long a0_ = 0ull, a1_ = 0ull, a2_ = 0ull, a3_ = 0ull;                 \
    const unsigned sa_ = rb_ + khoff;                                                  \
    _Pragma("unroll")                                                                  \
    for (int i_ = 0; i_ < 8; i_++) {                                                   \
        unsigned long long va_, vb_;                                                   \
        asm volatile("ld.shared.v2.u64 {%0, %1}, [%2];"                                \
                     : "=l"(va_), "=l"(vb_) : "r"(sa_ + 16u * i_));                    \
        if (i_ & 1) {                                                                  \
            asm("fma.rn.f32x2 %0, %1, %2, %0;" : "+l"(a2_) : "l"(va_), "l"(Ep[2*i_]));   \
            asm("fma.rn.f32x2 %0, %1, %2, %0;" : "+l"(a3_) : "l"(vb_), "l"(Ep[2*i_+1])); \
        } else {                                                                       \
            asm("fma.rn.f32x2 %0, %1, %2, %0;" : "+l"(a0_) : "l"(va_), "l"(Ep[2*i_]));   \
            asm("fma.rn.f32x2 %0, %1, %2, %0;" : "+l"(a1_) : "l"(vb_), "l"(Ep[2*i_+1])); \
        }                                                                              \
    }                                                                                  \
    asm("add.rn.f32x2 %0, %0, %1;" : "+l"(a0_) : "l"(a2_));                            \
    asm("add.rn.f32x2 %0, %0, %1;" : "+l"(a1_) : "l"(a3_));                            \
    asm("add.rn.f32x2 %0, %0, %1;" : "+l"(a0_) : "l"(a1_));                            \
    float lo_, hi_;                                                                    \
    asm("mov.b64 {%0, %1}, %2;" : "=f"(lo_), "=f"(hi_) : "l"(a0_));                    \
    float p_ = lo_ + hi_;                                                              \
    p_ += __shfl_xor_sync(0xffffffffu, p_, 1);                                         \
    if (kh == 0) {                                                                     \
        u = RESC ? (p_ * ee_ * r_) : (p_ * ee_);                                       \
        asm volatile("st.shared.f32 [%0], %1;"                                         \
                     :: "r"(ub + (unsigned)((PAR) * 288) + stoff), "f"(u));            \
        if (o == tg_) gold += (eraw) + tm_sh[tg_ * NL + tgprev];                       \
    }                                                                                  \
    tgprev = tg_;                                                                      \
} while (0)

__global__ __launch_bounds__(256, 1) void crf_forward_kernel(
    const float* __restrict__ scores, const int* __restrict__ targets,
    const float* __restrict__ startv, const float* __restrict__ Tmat,
    const float* __restrict__ endv)
{
    __shared__ float tm_sh[NL * NL];                 // gold-path transition gather
    __shared__ int   tg_sh[2][NT];                   // targets per batch
    __shared__ __align__(16) float usm[2][144];      // per batch: 2 bufs x (32 + pad + 32) floats
    __shared__ float sh_m[2];
    __shared__ float red[2][4], redg[2][4];

    const int tid = threadIdx.x;
    const int sub = tid >> 7;            // batch within CTA
    const int wb  = (tid >> 5) & 3;      // warp within batch
    const int l   = tid & 31;
    const int o   = wb * 16 + (l >> 1);  // output state owned by this lane pair
    const int kh  = l & 1;               // K-half
    const int b   = blockIdx.x * 2 + sub;

    for (int i = tid; i < NL * NL; i += 256) tm_sh[i] = Tmat[i];
    for (int i = (tid & 127); i < NT; i += 128) tg_sh[sub][i] = targets[b * NT + i];

    // E slice for this lane: exp(T_mat[o][kh*32 + k]), packed as f32x2
    unsigned long long Ep[16];
#pragma unroll
    for (int j = 0; j < 16; j++) {
        float e0 = __expf(Tmat[o * NL + kh * 32 + 2 * j]);
        float e1 = __expf(Tmat[o * NL + kh * 32 + 2 * j + 1]);
        asm("mov.b64 %0, {%1, %2};" : "=l"(Ep[j]) : "f"(e0), "f"(e1));
    }

    const unsigned ub    = (unsigned)__cvta_generic_to_shared(&usm[sub][0]);
    const unsigned khoff = (unsigned)(kh * 144);
    const unsigned stoff = (unsigned)((o < 32) ? 4 * o : 144 + 4 * (o - 32));

    // t = 0 init
    const float emit0 = scores[((size_t)b * NT) * NL + o];
    const float prev0 = startv[o] + emit0;
    float gold = 0.0f;
    int tgprev = targets[b * NT];
    if (kh == 0 && o == tgprev) gold = prev0;
    if ((tid & 127) == 0) sh_m[sub] = prev0;       // anchor = prev0[state 0]
    __syncthreads();
    const float m0 = sh_m[sub];
    double Mac = (double)m0;
    float u = 0.0f;
    if (kh == 0) {
        u = __expf(prev0 - m0);
        asm volatile("st.shared.f32 [%0], %1;" :: "r"(ub + stoff), "f"(u)); // buf0 = u(0)
    }

    // emit prefetch (kh==0 lanes only)
    const float* sb = scores + (size_t)b * NT * NL + o;
    float e0r = 0.f, e1r = 0.f, e2r = 0.f, e3r = 0.f;
    if (kh == 0) {
        e0r = sb[1 * NL]; e1r = sb[2 * NL]; e2r = sb[3 * NL]; e3r = sb[4 * NL];
    }

#pragma unroll 1
    for (int t = 1; t <= NT - 7; t += 4) {   // covers t = 1..1020; t always odd
        CRF_STEP(t,     1, e0r, 1); if (kh == 0) e0r = sb[(size_t)(t + 4) * NL];
        CRF_STEP(t + 1, 0, e1r, 0); if (kh == 0) e1r = sb[(size_t)(t + 5) * NL];
        CRF_STEP(t + 2, 1, e2r, 0); if (kh == 0) e2r = sb[(size_t)(t + 6) * NL];
        CRF_STEP(t + 3, 0, e3r, 0); if (kh == 0) e3r = (t + 7 <= NT - 1)
                                                       ? sb[(size_t)(t + 7) * NL] : 0.f;
    }
    CRF_STEP(1021, 1, e0r, 0);
    CRF_STEP(1022, 0, e1r, 0);
    CRF_STEP(1023, 1, e2r, 0);

    // normalizer = Mac + log(sum_o u[o] * e^{end[o]}); gold end term
    float wv = 0.0f;
    if (kh == 0) {
        wv = u * __expf(endv[o]);
        if (o == tgprev) gold += endv[o];
    }
    const float s1 = warp_sum(wv);
    const float g1 = warp_sum(gold);
    if (l == 0) { red[sub][wb] = s1; redg[sub][wb] = g1; }
    __syncthreads();
    if ((tid & 127) == 0) {
        const float ssum = red[sub][0] + red[sub][1] + red[sub][2] + red[sub][3];
        const float gg   = redg[sub][0] + redg[sub][1] + redg[sub][2] + redg[sub][3];
        g_loss[b] = (float)(Mac + (double)__logf(ssum)) - gg;
    }
}

__global__ void crf_reduce_kernel(float* __restrict__ out) {
    __shared__ float w[8];
    const int i = threadIdx.x;
    float v = g_loss[i];
#pragma unroll
    for (int k = 16; k; k >>= 1) v += __shfl_xor_sync(0xffffffffu, v, k);
    if ((i & 31) == 0) w[i >> 5] = v;
    __syncthreads();
    if (i == 0) {
        float s = 0.0f;
#pragma unroll
        for (int k = 0; k < 8; k++) s += w[k];
        out[0] = s * (1.0f / (float)NB);
    }
}

extern "C" void kernel_launch(void* const* d_in, const int* in_sizes, int n_in,
                              void* d_out, int out_size)
{
    const float* scores  = (const float*)d_in[0];
    const int*   targets = (const int*)d_in[1];
    const float* startv  = (const float*)d_in[2];
    const float* Tmat    = (const float*)d_in[3];
    const float* endv    = (const float*)d_in[4];

    crf_forward_kernel<<<NB / 2, 256>>>(scores, targets, startv, Tmat, endv);
    crf_reduce_kernel<<<1, NB>>>((float*)d_out);
}

// round 4
// speedup vs baseline: 1.1675x; 1.1302x over previous
#include <cuda_runtime.h>

#define NB 256
#define NT 1024
#define NL 64

__device__ float g_loss[NB];

__device__ __forceinline__ float warp_sum(float v) {
#pragma unroll
    for (int k = 16; k; k >>= 1) v += __shfl_xor_sync(0xffffffffu, v, k);
    return v;
}

// One scan step, fully intra-warp. Reads u(t-1) from buf[RD], writes u(t) to buf[RD^1].
// Lane owns output states o0=2l, o1=2l+1. E rows held in regs as f32x2 pairs.
// RESC: rescale by 1/u[0], accumulate log into Mac (every 4th step).
#define CRF_STEP(t, RD, epk, RESC) do {                                                \
    const int tg_ = tg_sh[sub][(t)];                                                   \
    const float ee0_ = __expf((epk).x);                                                \
    const float ee1_ = __expf((epk).y);                                                \
    const unsigned rb_ = ub + (unsigned)((RD) * 256);                                  \
    float r_ = 1.0f;                                                                   \
    if (RESC) {                                                                        \
        float u0_;                                                                     \
        asm volatile("ld.shared.f32 %0, [%1];" : "=f"(u0_) : "r"(rb_));                \
        asm("rcp.approx.f32 %0, %1;" : "=f"(r_) : "f"(u0_));                           \
        Mac += (double)__logf(u0_);                                                    \
    }                                                                                  \
    unsigned long long a0_ = 0ull, a1_ = 0ull, a2_ = 0ull, a3_ = 0ull;                 \
    _Pragma("unroll")                                                                  \
    for (int j_ = 0; j_ < 16; j_++) {                                                  \
        unsigned long long va_, vb_;                                                   \
        asm volatile("ld.shared.v2.u64 {%0, %1}, [%2];"                                \
                     : "=l"(va_), "=l"(vb_) : "r"(rb_ + 16u * j_));                    \
        asm("fma.rn.f32x2 %0, %1, %2, %0;" : "+l"(a0_) : "l"(va_), "l"(E0[2*j_]));     \
        asm("fma.rn.f32x2 %0, %1, %2, %0;" : "+l"(a1_) : "l"(vb_), "l"(E0[2*j_+1]));   \
        asm("fma.rn.f32x2 %0, %1, %2, %0;" : "+l"(a2_) : "l"(va_), "l"(E1[2*j_]));     \
        asm("fma.rn.f32x2 %0, %1, %2, %0;" : "+l"(a3_) : "l"(vb_), "l"(E1[2*j_+1]));   \
    }                                                                                  \
    asm("add.rn.f32x2 %0, %0, %1;" : "+l"(a0_) : "l"(a1_));                            \
    asm("add.rn.f32x2 %0, %0, %1;" : "+l"(a2_) : "l"(a3_));                            \
    float x0_, y0_, x1_, y1_;                                                          \
    asm("mov.b64 {%0, %1}, %2;" : "=f"(x0_), "=f"(y0_) : "l"(a0_));                    \
    asm("mov.b64 {%0, %1}, %2;" : "=f"(x1_), "=f"(y1_) : "l"(a2_));                    \
    if (RESC) { u0r = (x0_ + y0_) * ee0_ * r_; u1r = (x1_ + y1_) * ee1_ * r_; }        \
    else      { u0r = (x0_ + y0_) * ee0_;      u1r = (x1_ + y1_) * ee1_; }             \
    unsigned long long up_;                                                            \
    asm("mov.b64 %0, {%1, %2};" : "=l"(up_) : "f"(u0r), "f"(u1r));                     \
    asm volatile("st.shared.u64 [%0], %1;"                                             \
                 :: "r"(ub + (unsigned)(((RD) ^ 1) * 256) + 8u * (unsigned)l),         \
                    "l"(up_));                                                         \
    if (o0 == tg_)      gold += (epk).x + tm_sh[tg_ * NL + tgprev];                    \
    else if (o1 == tg_) gold += (epk).y + tm_sh[tg_ * NL + tgprev];                    \
    tgprev = tg_;                                                                      \
    __syncwarp();                                                                      \
} while (0)

__global__ __launch_bounds__(64, 1) void crf_forward_kernel(
    const float* __restrict__ scores, const int* __restrict__ targets,
    const float* __restrict__ startv, const float* __restrict__ Tmat,
    const float* __restrict__ endv)
{
    __shared__ float tm_sh[NL * NL];                 // T_mat (gold gather + E build)
    __shared__ int   tg_sh[2][NT];                   // targets, one slab per warp/batch
    __shared__ __align__(16) float usm[2][2][NL];    // [warp][parity][state]

    const int tid = threadIdx.x;
    const int sub = tid >> 5;          // warp = batch within CTA
    const int l   = tid & 31;
    const int b   = blockIdx.x * 2 + sub;
    const int o0  = 2 * l, o1 = 2 * l + 1;

    for (int i = tid; i < NL * NL; i += 64) tm_sh[i] = Tmat[i];
    for (int i = l; i < NT; i += 32) tg_sh[sub][i] = targets[b * NT + i];
    __syncthreads();                   // the ONLY CTA-wide barrier before the loop

    // E rows for this lane's two output states: E[o][k] = exp(T_mat[o][k])
    unsigned long long E0[32], E1[32];
#pragma unroll
    for (int j = 0; j < 32; j++) {
        float a0 = __expf(tm_sh[o0 * NL + 2 * j]);
        float a1 = __expf(tm_sh[o0 * NL + 2 * j + 1]);
        asm("mov.b64 %0, {%1, %2};" : "=l"(E0[j]) : "f"(a0), "f"(a1));
        float c0 = __expf(tm_sh[o1 * NL + 2 * j]);
        float c1 = __expf(tm_sh[o1 * NL + 2 * j + 1]);
        asm("mov.b64 %0, {%1, %2};" : "=l"(E1[j]) : "f"(c0), "f"(c1));
    }

    const unsigned ub = (unsigned)__cvta_generic_to_shared(&usm[sub][0][0]);

    // ---- t = 0 init ----
    const float2* sb2 = reinterpret_cast<const float2*>(scores + (size_t)b * NT * NL) + l;
    const float2 em0 = sb2[0];
    const float p0x = startv[o0] + em0.x;
    const float p0y = startv[o1] + em0.y;
    const float m0  = __shfl_sync(0xffffffffu, p0x, 0);   // anchor = prev0[state 0]
    double Mac = (double)m0;
    float gold = 0.0f;
    int tgprev = tg_sh[sub][0];
    if (o0 == tgprev)      gold = p0x;
    else if (o1 == tgprev) gold = p0y;

    float u0r = __expf(p0x - m0);
    float u1r = __expf(p0y - m0);
    {
        unsigned long long up;
        asm("mov.b64 %0, {%1, %2};" : "=l"(up) : "f"(u0r), "f"(u1r));
        asm volatile("st.shared.u64 [%0], %1;"
                     :: "r"(ub + 8u * (unsigned)l), "l"(up));   // buf 0 = u(0)
    }
    __syncwarp();

    // emit prefetch, depth 4 (one float2 LDG per step per lane)
    float2 e0p = sb2[1 * 32];
    float2 e1p = sb2[2 * 32];
    float2 e2p = sb2[3 * 32];
    float2 e3p = sb2[4 * 32];

#pragma unroll 1
    for (int t = 1; t <= NT - 7; t += 4) {   // covers t = 1..1020; t always odd
        CRF_STEP(t,     0, e0p, 1); e0p = sb2[(size_t)(t + 4) * 32];
        CRF_STEP(t + 1, 1, e1p, 0); e1p = sb2[(size_t)(t + 5) * 32];
        CRF_STEP(t + 2, 0, e2p, 0); e2p = sb2[(size_t)(t + 6) * 32];
        CRF_STEP(t + 3, 1, e3p, 0); e3p = (t + 7 <= NT - 1)
                                          ? sb2[(size_t)(t + 7) * 32]
                                          : make_float2(0.f, 0.f);
    }
    CRF_STEP(1021, 0, e0p, 0);
    CRF_STEP(1022, 1, e1p, 0);
    CRF_STEP(1023, 0, e2p, 0);

    // ---- finalize: normalizer = Mac + log(sum_o u[o] e^{end[o]}), gold end term ----
    float wv = u0r * __expf(endv[o0]) + u1r * __expf(endv[o1]);
    if (o0 == tgprev)      gold += endv[o0];
    else if (o1 == tgprev) gold += endv[o1];
    const float s = warp_sum(wv);
    const float g = warp_sum(gold);
    if (l == 0)
        g_loss[b] = (float)(Mac + (double)__logf(s)) - g;
}

__global__ void crf_reduce_kernel(float* __restrict__ out) {
    __shared__ float w[8];
    const int i = threadIdx.x;
    float v = g_loss[i];
#pragma unroll
    for (int k = 16; k; k >>= 1) v += __shfl_xor_sync(0xffffffffu, v, k);
    if ((i & 31) == 0) w[i >> 5] = v;
    __syncthreads();
    if (i == 0) {
        float s = 0.0f;
#pragma unroll
        for (int k = 0; k < 8; k++) s += w[k];
        out[0] = s * (1.0f / (float)NB);
    }
}

extern "C" void kernel_launch(void* const* d_in, const int* in_sizes, int n_in,
                              void* d_out, int out_size)
{
    const float* scores  = (const float*)d_in[0];
    const int*   targets = (const int*)d_in[1];
    const float* startv  = (const float*)d_in[2];
    const float* Tmat    = (const float*)d_in[3];
    const float* endv    = (const float*)d_in[4];

    crf_forward_kernel<<<NB / 2, 64>>>(scores, targets, startv, Tmat, endv);
    crf_reduce_kernel<<<1, NB>>>((float*)d_out);
}

// round 6
// speedup vs baseline: 1.7850x; 1.5289x over previous
#include <cuda_runtime.h>

#define NB 256
#define NT 1024
#define NL 64

__device__ float g_norm[NB];
__device__ float g_gold[NB];

__device__ __forceinline__ float warp_sum(float v) {
#pragma unroll
    for (int k = 16; k; k >>= 1) v += __shfl_xor_sync(0xffffffffu, v, k);
    return v;
}

// One scan step, intra-warp, no volatile: plain smem ops ordered by __syncwarp.
// Reads u(t-1) from buf[RD], writes u(t) to buf[RD^1]. Lane owns states 2l, 2l+1.
#define CRF_STEP(t, RD, epk, RESC) do {                                                \
    const float ee0_ = __expf((epk).x);                                                \
    const float ee1_ = __expf((epk).y);                                                \
    const float* rbuf_ = usm[sub][(RD)];                                               \
    float r_ = 1.0f;                                                                   \
    if (RESC) {                                                                        \
        const float u0_ = rbuf_[0];                                                    \
        asm("rcp.approx.f32 %0, %1;" : "=f"(r_) : "f"(u0_));                           \
        Mac += (double)__logf(u0_);                                                    \
    }                                                                                  \
    unsigned long long a0_ = 0ull, a1_ = 0ull, a2_ = 0ull, a3_ = 0ull;                 \
    const ulonglong2* rp_ = (const ulonglong2*)rbuf_;                                  \
    _Pragma("unroll")                                                                  \
    for (int j_ = 0; j_ < 16; j_++) {                                                  \
        const ulonglong2 v_ = rp_[j_];                                                 \
        asm("fma.rn.f32x2 %0, %1, %2, %0;" : "+l"(a0_) : "l"(v_.x), "l"(E0[2*j_]));    \
        asm("fma.rn.f32x2 %0, %1, %2, %0;" : "+l"(a1_) : "l"(v_.y), "l"(E0[2*j_+1]));  \
        asm("fma.rn.f32x2 %0, %1, %2, %0;" : "+l"(a2_) : "l"(v_.x), "l"(E1[2*j_]));    \
        asm("fma.rn.f32x2 %0, %1, %2, %0;" : "+l"(a3_) : "l"(v_.y), "l"(E1[2*j_+1]));  \
    }                                                                                  \
    asm("add.rn.f32x2 %0, %0, %1;" : "+l"(a0_) : "l"(a1_));                            \
    asm("add.rn.f32x2 %0, %0, %1;" : "+l"(a2_) : "l"(a3_));                            \
    float x0_, y0_, x1_, y1_;                                                          \
    asm("mov.b64 {%0, %1}, %2;" : "=f"(x0_), "=f"(y0_) : "l"(a0_));                    \
    asm("mov.b64 {%0, %1}, %2;" : "=f"(x1_), "=f"(y1_) : "l"(a2_));                    \
    if (RESC) { u0r = (x0_ + y0_) * ee0_ * r_; u1r = (x1_ + y1_) * ee1_ * r_; }        \
    else      { u0r = (x0_ + y0_) * ee0_;      u1r = (x1_ + y1_) * ee1_; }             \
    unsigned long long up_;                                                            \
    asm("mov.b64 %0, {%1, %2};" : "=l"(up_) : "f"(u0r), "f"(u1r));                     \
    ((unsigned long long*)usm[sub][(RD) ^ 1])[l] = up_;                                \
    __syncwarp();                                                                      \
} while (0)

__global__ __launch_bounds__(64, 1) void crf_main_kernel(
    const float* __restrict__ scores, const int* __restrict__ targets,
    const float* __restrict__ startv, const float* __restrict__ Tmat,
    const float* __restrict__ endv)
{
    // ---------------- gold-path CTAs (blockIdx 128..131) ----------------
    if (blockIdx.x >= NB / 2) {
        const int b = (blockIdx.x - NB / 2) * 64 + threadIdx.x;   // 0..255
        const float* sc = scores + (size_t)b * NT * NL;
        const int*   tg = targets + (size_t)b * NT;
        int tp = tg[0];
        float g = startv[tp] + sc[tp];            // start + emit(t=0)
#pragma unroll 8
        for (int t = 1; t < NT; t++) {
            const int c = tg[t];
            g += sc[(size_t)t * NL + c] + Tmat[c * NL + tp];
            tp = c;
        }
        g_gold[b] = g + endv[tp];
        return;
    }

    // ---------------- forward CTAs: warp = one batch chain ----------------
    __shared__ __align__(16) float usm[2][2][NL];   // [warp][parity][state]

    const int tid = threadIdx.x;
    const int sub = tid >> 5;
    const int l   = tid & 31;
    const int b   = blockIdx.x * 2 + sub;
    const int o0  = 2 * l, o1 = 2 * l + 1;

    // E rows for this lane's two output states: E[o][k] = exp(T_mat[o][k])
    unsigned long long E0[32], E1[32];
#pragma unroll
    for (int j = 0; j < 32; j++) {
        const float a0 = __expf(__ldg(&Tmat[o0 * NL + 2 * j]));
        const float a1 = __expf(__ldg(&Tmat[o0 * NL + 2 * j + 1]));
        asm("mov.b64 %0, {%1, %2};" : "=l"(E0[j]) : "f"(a0), "f"(a1));
        const float c0 = __expf(__ldg(&Tmat[o1 * NL + 2 * j]));
        const float c1 = __expf(__ldg(&Tmat[o1 * NL + 2 * j + 1]));
        asm("mov.b64 %0, {%1, %2};" : "=l"(E1[j]) : "f"(c0), "f"(c1));
    }

    // ---- t = 0 init ----
    const float2* sb2 = reinterpret_cast<const float2*>(scores + (size_t)b * NT * NL) + l;
    const float2 em0 = sb2[0];
    const float p0x = startv[o0] + em0.x;
    const float p0y = startv[o1] + em0.y;
    const float m0  = __shfl_sync(0xffffffffu, p0x, 0);   // anchor = prev0[state 0]
    double Mac = (double)m0;

    float u0r = __expf(p0x - m0);
    float u1r = __expf(p0y - m0);
    {
        unsigned long long up;
        asm("mov.b64 %0, {%1, %2};" : "=l"(up) : "f"(u0r), "f"(u1r));
        ((unsigned long long*)usm[sub][0])[l] = up;       // buf 0 = u(0)
    }
    __syncwarp();

    // emit prefetch, depth 4
    float2 e0p = sb2[1 * 32];
    float2 e1p = sb2[2 * 32];
    float2 e2p = sb2[3 * 32];
    float2 e3p = sb2[4 * 32];

#pragma unroll 1
    for (int t = 1; t <= NT - 7; t += 4) {   // covers t = 1..1020
        CRF_STEP(t,     0, e0p, 1); e0p = sb2[(size_t)(t + 4) * 32];
        CRF_STEP(t + 1, 1, e1p, 0); e1p = sb2[(size_t)(t + 5) * 32];
        CRF_STEP(t + 2, 0, e2p, 0); e2p = sb2[(size_t)(t + 6) * 32];
        CRF_STEP(t + 3, 1, e3p, 0); e3p = (t + 7 <= NT - 1)
                                          ? sb2[(size_t)(t + 7) * 32]
                                          : make_float2(0.f, 0.f);
    }
    CRF_STEP(1021, 0, e0p, 0);
    CRF_STEP(1022, 1, e1p, 0);
    CRF_STEP(1023, 0, e2p, 0);

    // normalizer = Mac + log( sum_o u[o] * e^{end[o]} )
    const float wv = u0r * __expf(endv[o0]) + u1r * __expf(endv[o1]);
    const float s = warp_sum(wv);
    if (l == 0)
        g_norm[b] = (float)(Mac + (double)__logf(s));
}

__global__ void crf_reduce_kernel(float* __restrict__ out) {
    __shared__ float w[8];
    const int i = threadIdx.x;
    float v = g_norm[i] - g_gold[i];
#pragma unroll
    for (int k = 16; k; k >>= 1) v += __shfl_xor_sync(0xffffffffu, v, k);
    if ((i & 31) == 0) w[i >> 5] = v;
    __syncthreads();
    if (i == 0) {
        float s = 0.0f;
#pragma unroll
        for (int k = 0; k < 8; k++) s += w[k];
        out[0] = s * (1.0f / (float)NB);
    }
}

extern "C" void kernel_launch(void* const* d_in, const int* in_sizes, int n_in,
                              void* d_out, int out_size)
{
    const float* scores  = (const float*)d_in[0];
    const int*   targets = (const int*)d_in[1];
    const float* startv  = (const float*)d_in[2];
    const float* Tmat    = (const float*)d_in[3];
    const float* endv    = (const float*)d_in[4];

    crf_main_kernel<<<NB / 2 + 4, 64>>>(scores, targets, startv, Tmat, endv);
    crf_reduce_kernel<<<1, NB>>>((float*)d_out);
}